// round 4
// baseline (speedup 1.0000x reference)
#include <cuda_runtime.h>
#include <math.h>

#define NB     2
#define SEQ    2048
#define HID    1024
#define NH     16
#define HD     64
#define SCALE  0.25f      /* 1/sqrt(64) / temperature(0.5) */
#define THRESH 0.01f
#define TQ     16
#define PAD_S  2056       /* sS row stride (2048 + 8) */

typedef unsigned long long u64;

#define SPLAT(dst, f)   asm("mov.b64 %0, {%1, %1};" : "=l"(dst) : "f"(f))
#define FMA2(acc, a, b) asm("fma.rn.f32x2 %0, %1, %2, %0;" : "+l"(acc) : "l"(a), "l"(b))
#define UNPK(lo, hi, v) asm("mov.b64 {%0, %1}, %2;" : "=f"(lo), "=f"(hi) : "l"(v))

/* scratch: projected tensors. K is stored TRANSPOSED: [b][h][d][s] */
__device__ float g_q [NB * NH * SEQ * HD];
__device__ float g_kT[NB * NH * HD * SEQ];
__device__ float g_v [NB * NH * SEQ * HD];

/* ------------------------------------------------------------------ */
/* Projection: C[i][o] = sum_k X[i][k]*W[o][k] + b[o].                 */
/* 64x64 tile / 256 threads, 4x4 per thread via FFMA2 pairs.           */
/* z==1 (K) scatters transposed to g_kT; z==0/2 scatter [b][h][s][d].  */
/* ------------------------------------------------------------------ */
__global__ __launch_bounds__(256) void proj_kernel(
    const float* __restrict__ X0, const float* __restrict__ W0, const float* __restrict__ b0,
    const float* __restrict__ X1, const float* __restrict__ W1, const float* __restrict__ b1,
    const float* __restrict__ X2, const float* __restrict__ W2, const float* __restrict__ b2)
{
    const int z = blockIdx.z;
    const float* X    = (z == 0) ? X0 : (z == 1) ? X1 : X2;
    const float* W    = (z == 0) ? W0 : (z == 1) ? W1 : W2;
    const float* bias = (z == 0) ? b0 : (z == 1) ? b1 : b2;

    const int i0 = blockIdx.x * 64;
    const int o0 = blockIdx.y * 64;

    __shared__ float Xs[16][68];
    __shared__ float Ws[16][68];

    const int tid = threadIdx.x;
    const int to  = tid & 15;
    const int ti  = tid >> 4;

    u64 acc2[4][2];
#pragma unroll
    for (int ii = 0; ii < 4; ii++) { acc2[ii][0] = 0ull; acc2[ii][1] = 0ull; }

    for (int k0 = 0; k0 < HID; k0 += 16) {
#pragma unroll
        for (int r = 0; r < 4; r++) {
            int idx = tid + r * 256;
            int row = idx >> 4, kk = idx & 15;
            Xs[kk][row] = X[(size_t)(i0 + row) * HID + k0 + kk];
            Ws[kk][row] = W[(size_t)(o0 + row) * HID + k0 + kk];
        }
        __syncthreads();
#pragma unroll
        for (int kk = 0; kk < 16; kk++) {
            float4 xv = *(const float4*)&Xs[kk][ti * 4];
            u64 w01 = *(const u64*)&Ws[kk][to * 4];
            u64 w23 = *(const u64*)&Ws[kk][to * 4 + 2];
            float ax[4] = {xv.x, xv.y, xv.z, xv.w};
#pragma unroll
            for (int ii = 0; ii < 4; ii++) {
                u64 a2; SPLAT(a2, ax[ii]);
                FMA2(acc2[ii][0], a2, w01);
                FMA2(acc2[ii][1], a2, w23);
            }
        }
        __syncthreads();
    }

    /* unpack + bias */
    float a[4][4];
#pragma unroll
    for (int ii = 0; ii < 4; ii++) {
        UNPK(a[ii][0], a[ii][1], acc2[ii][0]);
        UNPK(a[ii][2], a[ii][3], acc2[ii][1]);
    }
    const int obase = o0 + to * 4;
    const int head  = obase >> 6;
    const int dd0   = obase & 63;
    float4 bv = *(const float4*)&bias[obase];
    float bb4[4] = {bv.x, bv.y, bv.z, bv.w};

    if (z == 1) {
        /* transposed scatter: g_kT[((b*NH+head)*HD + dd)][s], f4 along s */
        const int i_first = i0 + ti * 4;
        const int batch   = i_first >> 11;
        const int s0      = i_first & 2047;
#pragma unroll
        for (int oo = 0; oo < 4; oo++) {
            float4 v;
            v.x = a[0][oo] + bb4[oo];
            v.y = a[1][oo] + bb4[oo];
            v.z = a[2][oo] + bb4[oo];
            v.w = a[3][oo] + bb4[oo];
            *(float4*)&g_kT[(((size_t)(batch * NH + head) * HD) + dd0 + oo) * SEQ + s0] = v;
        }
    } else {
        float* OUT = (z == 0) ? g_q : g_v;
#pragma unroll
        for (int ii = 0; ii < 4; ii++) {
            int i = i0 + ti * 4 + ii;
            int batch = i >> 11, s = i & 2047;
            float4 v;
            v.x = a[ii][0] + bb4[0];
            v.y = a[ii][1] + bb4[1];
            v.z = a[ii][2] + bb4[2];
            v.w = a[ii][3] + bb4[3];
            *(float4*)&OUT[(((size_t)(batch * NH + head) * SEQ + s) * HD) + dd0] = v;
        }
    }
}

/* ------------------------------------------------------------------ */
/* Attention: block = (b,h) x 16 q rows, 512 threads.                 */
/* smem: sS 16x2056 | sQT 64x20 | sKV (KT 64x260 / V 256x68) | mask    */
/* ------------------------------------------------------------------ */
#define QT_OFF  (16 * PAD_S)            /* 32896 */
#define KV_OFF  (QT_OFF + 64 * 20)      /* 34176 */
#define KV_F    17408                   /* max(64*260, 256*68) */
#define SM_F    (KV_OFF + KV_F)         /* 51584 floats */
#define SMEM_BYTES (SM_F * 4 + 2048)    /* + mask = 208384 B */

__global__ __launch_bounds__(512) void attn_kernel(
    const unsigned char* __restrict__ mask,
    float* __restrict__ w_out,                /* [B][NH][S][S] */
    float* __restrict__ o_out)                /* [B][S][HID]   */
{
    extern __shared__ float sm[];
    float* sS  = sm;
    float* sQT = sm + QT_OFF;
    float* sKV = sm + KV_OFF;
    unsigned char* sMask = (unsigned char*)(sm + SM_F);

    const int bh = blockIdx.y;
    const int batch = bh >> 4;
    const int h  = bh & 15;
    const int q0 = blockIdx.x * TQ;
    const int tid = threadIdx.x;

    const float* Q  = g_q  + (size_t)bh * SEQ * HD;
    const float* KT = g_kT + (size_t)bh * HD * SEQ;
    const float* V  = g_v  + (size_t)bh * SEQ * HD;

    for (int i = tid; i < SEQ; i += 512) sMask[i] = mask[batch * SEQ + i];
    for (int idx = tid; idx < TQ * HD; idx += 512) {
        int q = idx >> 6, dd = idx & 63;
        sQT[dd * 20 + q] = Q[(size_t)(q0 + q) * HD + dd];
    }
    __syncthreads();

    /* ---------------- pass 1: scores = (Q K^T) * SCALE --------------- */
    {
        const int kg = tid & 127;     /* 128 f2 key-groups = 256 keys */
        const int qg = tid >> 7;      /* 4 q-groups of 4              */
        for (int kt = 0; kt < SEQ; kt += 256) {
            /* load K^T tile: 64 dd x 256 keys, pad 260 */
#pragma unroll
            for (int r = 0; r < 8; r++) {
                int idx = tid + r * 512;           /* 4096 f4 units */
                int dd = idx >> 6, k4 = idx & 63;
                *(float4*)&sKV[dd * 260 + k4 * 4] =
                    *(const float4*)&KT[(size_t)dd * SEQ + kt + k4 * 4];
            }
            __syncthreads();

            u64 acc2[2][2];
            acc2[0][0] = acc2[0][1] = acc2[1][0] = acc2[1][1] = 0ull;
#pragma unroll 16
            for (int dd = 0; dd < 64; dd++) {
                float2 kv = *(const float2*)&sKV[dd * 260 + kg * 2];
                ulonglong2 qp = *(const ulonglong2*)&sQT[dd * 20 + qg * 4];
                u64 k0s, k1s;
                SPLAT(k0s, kv.x); SPLAT(k1s, kv.y);
                FMA2(acc2[0][0], k0s, qp.x);
                FMA2(acc2[0][1], k0s, qp.y);
                FMA2(acc2[1][0], k1s, qp.x);
                FMA2(acc2[1][1], k1s, qp.y);
            }

            float a00, a01, a02, a03, a10, a11, a12, a13;
            UNPK(a00, a01, acc2[0][0]);   /* key0: q0,q1 */
            UNPK(a02, a03, acc2[0][1]);   /* key0: q2,q3 */
            UNPK(a10, a11, acc2[1][0]);   /* key1: q0,q1 */
            UNPK(a12, a13, acc2[1][1]);

            const int col = kt + kg * 2;
            const bool m0 = (sMask[col] != 0), m1 = (sMask[col + 1] != 0);
            float2 st;
            st.x = m0 ? -1e30f : a00 * SCALE;  st.y = m1 ? -1e30f : a10 * SCALE;
            *(float2*)&sS[(qg * 4 + 0) * PAD_S + col] = st;
            st.x = m0 ? -1e30f : a01 * SCALE;  st.y = m1 ? -1e30f : a11 * SCALE;
            *(float2*)&sS[(qg * 4 + 1) * PAD_S + col] = st;
            st.x = m0 ? -1e30f : a02 * SCALE;  st.y = m1 ? -1e30f : a12 * SCALE;
            *(float2*)&sS[(qg * 4 + 2) * PAD_S + col] = st;
            st.x = m0 ? -1e30f : a03 * SCALE;  st.y = m1 ? -1e30f : a13 * SCALE;
            *(float2*)&sS[(qg * 4 + 3) * PAD_S + col] = st;
            __syncthreads();
        }
    }

    /* ------- softmax + prune + L1 renorm + write weights (1 warp/row) */
    {
        const int r = tid >> 5, lane = tid & 31;
        float* row = &sS[r * PAD_S];

        float M = -1e30f;
        for (int c = lane; c < SEQ; c += 32) M = fmaxf(M, row[c]);
#pragma unroll
        for (int o = 16; o; o >>= 1) M = fmaxf(M, __shfl_xor_sync(~0u, M, o));

        float D = 0.f;
        for (int c = lane; c < SEQ; c += 32) {
            float e = __expf(row[c] - M);
            row[c] = e;
            D += e;
        }
#pragma unroll
        for (int o = 16; o; o >>= 1) D += __shfl_xor_sync(~0u, D, o);

        const float thr = THRESH * D;     /* keep iff e/D >= 0.01 */
        float l1 = 0.f;
        for (int c = lane; c < SEQ; c += 32) {
            float e = row[c];
            if (e < thr) row[c] = 0.f;
            else         l1 += e;
        }
#pragma unroll
        for (int o = 16; o; o >>= 1) l1 += __shfl_xor_sync(~0u, l1, o);

        const float inv = 1.0f / fmaxf(l1, 1e-12f * D);

        float4* wrow = (float4*)&w_out[((size_t)bh * SEQ + (q0 + r)) * SEQ];
        for (int c4 = lane; c4 < SEQ / 4; c4 += 32) {
            float4 v = ((float4*)row)[c4];
            v.x *= inv; v.y *= inv; v.z *= inv; v.w *= inv;
            ((float4*)row)[c4] = v;
            wrow[c4] = v;
        }
    }
    __syncthreads();

    /* ---------------- pass 2: out = weights @ V (4-way k split) ------ */
    {
        const int dg = tid & 7;          /* d: [dg*4..+3] and [32+dg*4..+3] */
        const int q  = (tid >> 3) & 15;
        const int ks = tid >> 7;         /* 0..3 */

        u64 acc2[4] = {0ull, 0ull, 0ull, 0ull};

        for (int kt = 0; kt < SEQ; kt += 256) {
#pragma unroll
            for (int r = 0; r < 8; r++) {
                int idx = tid + r * 512;          /* 4096 f4 units */
                int k = idx >> 4, c4 = idx & 15;
                *(float4*)&sKV[k * 68 + c4 * 4] =
                    *(const float4*)&V[(size_t)(kt + k) * HD + c4 * 4];
            }
            __syncthreads();

            const int kbase = ks * 64;
#pragma unroll 8
            for (int kk = 0; kk < 64; kk += 4) {
                float4 wv = *(const float4*)&sS[q * PAD_S + kt + kbase + kk];
                float wa[4] = {wv.x, wv.y, wv.z, wv.w};
#pragma unroll
                for (int j = 0; j < 4; j++) {
                    const float* vrow = &sKV[(kbase + kk + j) * 68];
                    ulonglong2 vA = *(const ulonglong2*)&vrow[dg * 4];
                    ulonglong2 vB = *(const ulonglong2*)&vrow[32 + dg * 4];
                    u64 w2; SPLAT(w2, wa[j]);
                    FMA2(acc2[0], w2, vA.x);
                    FMA2(acc2[1], w2, vA.y);
                    FMA2(acc2[2], w2, vB.x);
                    FMA2(acc2[3], w2, vB.y);
                }
            }
            __syncthreads();
        }

        /* reduce over 4 k-splits through smem (reuse sKV) */
        float a[8];
        UNPK(a[0], a[1], acc2[0]);
        UNPK(a[2], a[3], acc2[1]);
        UNPK(a[4], a[5], acc2[2]);
        UNPK(a[6], a[7], acc2[3]);

        float* red = sKV;
        *(float4*)&red[tid * 8]     = *(float4*)&a[0];
        *(float4*)&red[tid * 8 + 4] = *(float4*)&a[4];
        __syncthreads();

        if (ks == 0) {
#pragma unroll
            for (int s = 1; s < 4; s++) {
                const float* p = &red[(tid + s * 128) * 8];
#pragma unroll
                for (int i = 0; i < 8; i++) a[i] += p[i];
            }
            float* op = &o_out[((size_t)(batch * SEQ + q0 + q) * HID) + h * HD];
            *(float4*)&op[dg * 4]      = *(float4*)&a[0];
            *(float4*)&op[32 + dg * 4] = *(float4*)&a[4];
        }
    }
}

/* ------------------------------------------------------------------ */
extern "C" void kernel_launch(void* const* d_in, const int* in_sizes, int n_in,
                              void* d_out, int out_size)
{
    const float* query = (const float*)d_in[0];
    const float* key   = (const float*)d_in[1];
    const float* value = (const float*)d_in[2];
    const unsigned char* mask = (const unsigned char*)d_in[3];
    const float* Wq = (const float*)d_in[4];
    const float* bq = (const float*)d_in[5];
    const float* Wk = (const float*)d_in[6];
    const float* bk = (const float*)d_in[7];
    const float* Wv = (const float*)d_in[8];
    const float* bv = (const float*)d_in[9];

    float* out = (float*)d_out;                       /* [B,S,H]    */
    float* wts = out + (size_t)NB * SEQ * HID;        /* [B,NH,S,S] */

    (void)in_sizes; (void)n_in; (void)out_size;

    {
        dim3 grid(64, 16, 3);
        proj_kernel<<<grid, 256>>>(query, Wq, bq, key, Wk, bk, value, Wv, bv);
    }
    {
        cudaFuncSetAttribute(attn_kernel,
                             cudaFuncAttributeMaxDynamicSharedMemorySize,
                             SMEM_BYTES);
        dim3 grid(SEQ / TQ, NB * NH);
        attn_kernel<<<grid, 512, SMEM_BYTES>>>(mask, wts, out);
    }
}

// round 5
// speedup vs baseline: 1.6253x; 1.6253x over previous
#include <cuda_runtime.h>
#include <math.h>

#define NB     2
#define SEQ    2048
#define HID    1024
#define NH     16
#define HD     64
#define SCALE  0.25f      /* 1/sqrt(64) / temperature(0.5) */
#define THRESH 0.01f
#define TQ     16
#define PAD_S  2056       /* sS row stride */

/* scratch: projected tensors. K stored TRANSPOSED: [b][h][d][s] */
__device__ float g_q [NB * NH * SEQ * HD];
__device__ float g_kT[NB * NH * HD * SEQ];
__device__ float g_v [NB * NH * SEQ * HD];

/* ------------------------------------------------------------------ */
/* Projection: C[i][o] = sum_k X[i][k]*W[o][k] + b[o].                 */
/* Tile 64 rows x 128 cols, 256 threads, 4x8 per thread (split cols).  */
/* z==1 (K) scatters transposed into g_kT.                             */
/* ------------------------------------------------------------------ */
__global__ __launch_bounds__(256) void proj_kernel(
    const float* __restrict__ X0, const float* __restrict__ W0, const float* __restrict__ b0,
    const float* __restrict__ X1, const float* __restrict__ W1, const float* __restrict__ b1,
    const float* __restrict__ X2, const float* __restrict__ W2, const float* __restrict__ b2)
{
    const int z = blockIdx.z;
    const float* X    = (z == 0) ? X0 : (z == 1) ? X1 : X2;
    const float* W    = (z == 0) ? W0 : (z == 1) ? W1 : W2;
    const float* bias = (z == 0) ? b0 : (z == 1) ? b1 : b2;

    const int i0 = blockIdx.x * 64;     /* 4096/64 = 64 */
    const int o0 = blockIdx.y * 128;    /* 1024/128 = 8 */

    __shared__ float Xs[16][68];
    __shared__ float Ws[16][132];

    const int tid = threadIdx.x;
    const int to  = tid & 15;           /* col group: cols to*4..+3 and 64+to*4..+3 */
    const int ti  = tid >> 4;           /* row group x4 */

    float acc[4][8] = {};

    for (int k0 = 0; k0 < HID; k0 += 16) {
#pragma unroll
        for (int r = 0; r < 4; r++) {
            int idx = tid + r * 256;                 /* 1024 */
            int row = idx >> 4, kk = idx & 15;
            Xs[kk][row] = X[(size_t)(i0 + row) * HID + k0 + kk];
        }
#pragma unroll
        for (int r = 0; r < 8; r++) {
            int idx = tid + r * 256;                 /* 2048 */
            int col = idx >> 4, kk = idx & 15;
            Ws[kk][col] = W[(size_t)(o0 + col) * HID + k0 + kk];
        }
        __syncthreads();
#pragma unroll
        for (int kk = 0; kk < 16; kk++) {
            float4 xv = *(const float4*)&Xs[kk][ti * 4];
            float4 w0 = *(const float4*)&Ws[kk][to * 4];
            float4 w1 = *(const float4*)&Ws[kk][64 + to * 4];
            float ax[4] = {xv.x, xv.y, xv.z, xv.w};
            float aw[8] = {w0.x, w0.y, w0.z, w0.w, w1.x, w1.y, w1.z, w1.w};
#pragma unroll
            for (int ii = 0; ii < 4; ii++)
#pragma unroll
                for (int oo = 0; oo < 8; oo++)
                    acc[ii][oo] += ax[ii] * aw[oo];
        }
        __syncthreads();
    }

    /* epilogue: bias + scatter */
    const int i_first = i0 + ti * 4;
    const int batch   = i_first >> 11;
    const int s0      = i_first & 2047;

#pragma unroll
    for (int g = 0; g < 2; g++) {
        const int obase = o0 + g * 64 + to * 4;
        const int head  = obase >> 6;
        const int dd0   = obase & 63;
        float4 bv = *(const float4*)&bias[obase];
        float bb4[4] = {bv.x, bv.y, bv.z, bv.w};

        if (z == 1) {
            /* transposed: g_kT[((b*NH+head)*HD + dd)][s] */
#pragma unroll
            for (int oo = 0; oo < 4; oo++) {
                float4 v;
                v.x = acc[0][g * 4 + oo] + bb4[oo];
                v.y = acc[1][g * 4 + oo] + bb4[oo];
                v.z = acc[2][g * 4 + oo] + bb4[oo];
                v.w = acc[3][g * 4 + oo] + bb4[oo];
                *(float4*)&g_kT[(((size_t)(batch * NH + head) * HD) + dd0 + oo) * SEQ + s0] = v;
            }
        } else {
            float* OUT = (z == 0) ? g_q : g_v;
#pragma unroll
            for (int ii = 0; ii < 4; ii++) {
                int s = s0 + ii;
                float4 v;
                v.x = acc[ii][g * 4 + 0] + bb4[0];
                v.y = acc[ii][g * 4 + 1] + bb4[1];
                v.z = acc[ii][g * 4 + 2] + bb4[2];
                v.w = acc[ii][g * 4 + 3] + bb4[3];
                *(float4*)&OUT[(((size_t)(batch * NH + head) * SEQ + s) * HD) + dd0] = v;
            }
        }
    }
}

/* ------------------------------------------------------------------ */
/* Attention: block = (b,h) x 16 q rows, 512 threads.                 */
/* smem: sS 16x2056 | sQT 64x20 | sKV (KT 64x260 / V 256x68 / red)    */
/* ------------------------------------------------------------------ */
#define QT_OFF  (16 * PAD_S)            /* 32896 */
#define KV_OFF  (QT_OFF + 64 * 20)      /* 34176 */
#define KV_F    17408                   /* max(64*260=16640, 256*68=17408) */
#define SM_F    (KV_OFF + KV_F)         /* 51584 floats */
#define SMEM_BYTES (SM_F * 4 + 2048)    /* 208384 B */

__global__ __launch_bounds__(512) void attn_kernel(
    const unsigned char* __restrict__ mask,
    float* __restrict__ w_out,                /* [B][NH][S][S] */
    float* __restrict__ o_out)                /* [B][S][HID]   */
{
    extern __shared__ float sm[];
    float* sS  = sm;
    float* sQT = sm + QT_OFF;
    float* sKV = sm + KV_OFF;
    unsigned char* sMask = (unsigned char*)(sm + SM_F);

    const int bh = blockIdx.y;
    const int batch = bh >> 4;
    const int h  = bh & 15;
    const int q0 = blockIdx.x * TQ;
    const int tid = threadIdx.x;

    const float* Q  = g_q  + (size_t)bh * SEQ * HD;
    const float* KT = g_kT + (size_t)bh * HD * SEQ;
    const float* V  = g_v  + (size_t)bh * SEQ * HD;

    for (int i = tid; i < SEQ; i += 512) sMask[i] = mask[batch * SEQ + i];
    for (int idx = tid; idx < TQ * HD; idx += 512) {
        int q = idx >> 6, dd = idx & 63;
        sQT[dd * 20 + q] = Q[(size_t)(q0 + q) * HD + dd];
    }
    __syncthreads();

    /* ------- pass 1: scores = (Q K^T)*SCALE; 4q x 4k per thread,
               dd split 2-way (ds), 256-key tiles ------------------- */
    {
        const int ds = tid >> 8;          /* 0/1 : dd 0..31 / 32..63 */
        const int qg = (tid >> 6) & 3;    /* q group of 4 */
        const int kg = tid & 63;          /* key group of 4 */

        for (int kt = 0; kt < SEQ; kt += 256) {
            /* stage K^T tile: 64 dd x 256 keys, row stride 260 */
#pragma unroll
            for (int r = 0; r < 8; r++) {
                int idx = tid + r * 512;             /* 4096 f4 units */
                int dd = idx >> 6, k4 = idx & 63;
                *(float4*)&sKV[dd * 260 + k4 * 4] =
                    *(const float4*)&KT[(size_t)dd * SEQ + kt + k4 * 4];
            }
            __syncthreads();

            float s[4][4] = {};
            const int dbase = ds * 32;
#pragma unroll 8
            for (int d2 = 0; d2 < 32; d2++) {
                const int dd = dbase + d2;
                float4 kv = *(const float4*)&sKV[dd * 260 + kg * 4];
                float4 qv = *(const float4*)&sQT[dd * 20 + qg * 4];
                float qa[4] = {qv.x, qv.y, qv.z, qv.w};
                float ka[4] = {kv.x, kv.y, kv.z, kv.w};
#pragma unroll
                for (int i = 0; i < 4; i++)
#pragma unroll
                    for (int j = 0; j < 4; j++)
                        s[i][j] += qa[i] * ka[j];
            }
            __syncthreads();            /* compute done; sKV reusable */

            float* red = sKV;           /* 16 x 256 floats */
            if (ds == 1) {
#pragma unroll
                for (int i = 0; i < 4; i++)
#pragma unroll
                    for (int j = 0; j < 4; j++)
                        red[(i * 4 + j) * 256 + (tid - 256)] = s[i][j];
            }
            __syncthreads();
            if (ds == 0) {
                const int col = kt + kg * 4;
                uchar4 m4 = *(const uchar4*)&sMask[col];
                unsigned char mm[4] = {m4.x, m4.y, m4.z, m4.w};
#pragma unroll
                for (int i = 0; i < 4; i++) {
                    float4 v;
                    float t0 = s[i][0] + red[(i * 4 + 0) * 256 + tid];
                    float t1 = s[i][1] + red[(i * 4 + 1) * 256 + tid];
                    float t2 = s[i][2] + red[(i * 4 + 2) * 256 + tid];
                    float t3 = s[i][3] + red[(i * 4 + 3) * 256 + tid];
                    v.x = mm[0] ? -1e30f : t0 * SCALE;
                    v.y = mm[1] ? -1e30f : t1 * SCALE;
                    v.z = mm[2] ? -1e30f : t2 * SCALE;
                    v.w = mm[3] ? -1e30f : t3 * SCALE;
                    *(float4*)&sS[(qg * 4 + i) * PAD_S + col] = v;
                }
            }
            __syncthreads();
        }
    }

    /* ------- softmax + prune + L1 renorm + write weights (1 warp/row) */
    {
        const int r = tid >> 5, lane = tid & 31;
        float* row = &sS[r * PAD_S];

        float M = -1e30f;
        for (int c = lane; c < SEQ; c += 32) M = fmaxf(M, row[c]);
#pragma unroll
        for (int o = 16; o; o >>= 1) M = fmaxf(M, __shfl_xor_sync(~0u, M, o));

        float D = 0.f;
        for (int c = lane; c < SEQ; c += 32) {
            float e = __expf(row[c] - M);
            row[c] = e;
            D += e;
        }
#pragma unroll
        for (int o = 16; o; o >>= 1) D += __shfl_xor_sync(~0u, D, o);

        const float thr = THRESH * D;     /* keep iff e/D >= 0.01 */
        float l1 = 0.f;
        for (int c = lane; c < SEQ; c += 32) {
            float e = row[c];
            if (e < thr) row[c] = 0.f;
            else         l1 += e;
        }
#pragma unroll
        for (int o = 16; o; o >>= 1) l1 += __shfl_xor_sync(~0u, l1, o);

        const float inv = 1.0f / fmaxf(l1, 1e-12f * D);

        float4* wrow = (float4*)&w_out[((size_t)bh * SEQ + (q0 + r)) * SEQ];
        for (int c4 = lane; c4 < SEQ / 4; c4 += 32) {
            float4 v = ((float4*)row)[c4];
            v.x *= inv; v.y *= inv; v.z *= inv; v.w *= inv;
            ((float4*)row)[c4] = v;
            wrow[c4] = v;
        }
    }
    __syncthreads();

    /* ------- pass 2: out = weights @ V; 4k x 8d per thread,
               4-way key split (ks), 256-key tiles ------------------ */
    {
        const int dg = tid & 7;           /* d: dg*4..+3 and 32+dg*4..+3 */
        const int q  = (tid >> 3) & 15;
        const int ks = tid >> 7;          /* 0..3 */

        float a[8] = {};

        for (int kt = 0; kt < SEQ; kt += 256) {
#pragma unroll
            for (int r = 0; r < 8; r++) {
                int idx = tid + r * 512;            /* 4096 f4 units */
                int k = idx >> 4, c4 = idx & 15;
                *(float4*)&sKV[k * 68 + c4 * 4] =
                    *(const float4*)&V[(size_t)(kt + k) * HD + c4 * 4];
            }
            __syncthreads();

            const int kbase = ks * 64;
#pragma unroll 4
            for (int kk = 0; kk < 64; kk += 4) {
                float4 wv = *(const float4*)&sS[q * PAD_S + kt + kbase + kk];
                float wa[4] = {wv.x, wv.y, wv.z, wv.w};
#pragma unroll
                for (int j = 0; j < 4; j++) {
                    const float* vrow = &sKV[(kbase + kk + j) * 68];
                    float4 vA = *(const float4*)&vrow[dg * 4];
                    float4 vB = *(const float4*)&vrow[32 + dg * 4];
                    a[0] += wa[j] * vA.x;
                    a[1] += wa[j] * vA.y;
                    a[2] += wa[j] * vA.z;
                    a[3] += wa[j] * vA.w;
                    a[4] += wa[j] * vB.x;
                    a[5] += wa[j] * vB.y;
                    a[6] += wa[j] * vB.z;
                    a[7] += wa[j] * vB.w;
                }
            }
            __syncthreads();
        }

        /* reduce over 4 ks splits via smem */
        float* red = sKV;
        *(float4*)&red[tid * 8]     = *(float4*)&a[0];
        *(float4*)&red[tid * 8 + 4] = *(float4*)&a[4];
        __syncthreads();

        if (ks == 0) {
#pragma unroll
            for (int s = 1; s < 4; s++) {
                const float* p = &red[(tid + s * 128) * 8];
#pragma unroll
                for (int i = 0; i < 8; i++) a[i] += p[i];
            }
            float* op = &o_out[((size_t)(batch * SEQ + q0 + q) * HID) + h * HD];
            *(float4*)&op[dg * 4]      = *(float4*)&a[0];
            *(float4*)&op[32 + dg * 4] = *(float4*)&a[4];
        }
    }
}

/* ------------------------------------------------------------------ */
extern "C" void kernel_launch(void* const* d_in, const int* in_sizes, int n_in,
                              void* d_out, int out_size)
{
    const float* query = (const float*)d_in[0];
    const float* key   = (const float*)d_in[1];
    const float* value = (const float*)d_in[2];
    const unsigned char* mask = (const unsigned char*)d_in[3];
    const float* Wq = (const float*)d_in[4];
    const float* bq = (const float*)d_in[5];
    const float* Wk = (const float*)d_in[6];
    const float* bk = (const float*)d_in[7];
    const float* Wv = (const float*)d_in[8];
    const float* bv = (const float*)d_in[9];

    float* out = (float*)d_out;                       /* [B,S,H]    */
    float* wts = out + (size_t)NB * SEQ * HID;        /* [B,NH,S,S] */

    (void)in_sizes; (void)n_in; (void)out_size;

    {
        dim3 grid(64, 8, 3);
        proj_kernel<<<grid, 256>>>(query, Wq, bq, key, Wk, bk, value, Wv, bv);
    }
    {
        cudaFuncSetAttribute(attn_kernel,
                             cudaFuncAttributeMaxDynamicSharedMemorySize,
                             SMEM_BYTES);
        dim3 grid(SEQ / TQ, NB * NH);
        attn_kernel<<<grid, 512, SMEM_BYTES>>>(mask, wts, out);
    }
}